// round 11
// baseline (speedup 1.0000x reference)
#include <cuda_runtime.h>
#include <cuda_fp16.h>

#define NN 100000
#define EE 3200000
#define HH 32
#define LL 4
#define GG 1000
#define CC 2
#define BN_EPS 1e-5f

#define FUSED_BLOCKS 1184          // 8 * 148 SMs
#define SCAN_B 98                  // ceil(100000 / 1024)

// ---------------- scratch (static device globals; no allocation) -------------
__device__ __half g_hh[NN * HH];        // node features (post-activation), fp16
__device__ float  g_z[NN * HH];         // agg, then pre-BN MLP output (fp32)
__device__ int    g_deg[NN];
__device__ int    g_rowptr[NN + 1];
__device__ int    g_cursor[NN];
__device__ int    g_csrc[EE];           // CSR-by-dst: source node per slot
__device__ int    g_blksum[SCAN_B];
__device__ float  g_pooled[GG * HH];
__device__ float  g_psum[FUSED_BLOCKS * HH];
__device__ float  g_psq [FUSED_BLOCKS * HH];
__device__ float  g_bn_a[HH];
__device__ float  g_bn_b[HH];

// ---------------- init (zero deg + pooled) + encoder, merged -----------------
__global__ void init_enc_kernel(const float* __restrict__ x,
                                const float* __restrict__ W_enc,
                                const float* __restrict__ b_enc) {
    int idx = blockIdx.x * blockDim.x + threadIdx.x;
    if (idx < NN) g_deg[idx] = 0;
    if (idx < GG * HH) g_pooled[idx] = 0.0f;
    if (idx < NN * 16) {                               // half2 index
        int i = idx >> 4;
        int k2 = idx & 15;
        float xv = x[i];
        float v0 = fmaf(xv, W_enc[2 * k2 + 0], b_enc[2 * k2 + 0]);
        float v1 = fmaf(xv, W_enc[2 * k2 + 1], b_enc[2 * k2 + 1]);
        *(__half2*)(g_hh + idx * 2) = __floats2half2_rn(v0, v1);
    }
}

// ---------------- CSR build --------------------------------------------------
__global__ void hist_kernel(const int* __restrict__ ei) {
    int e = blockIdx.x * blockDim.x + threadIdx.x;
    if (e >= EE) return;
    int d = ei[EE + e];                 // dst
    atomicAdd(&g_deg[d], 1);
}

__global__ void scan1_kernel() {
    __shared__ int sm[1024];
    int t = threadIdx.x;
    int idx = blockIdx.x * 1024 + t;
    int v = (idx < NN) ? g_deg[idx] : 0;
    sm[t] = v;
    __syncthreads();
    #pragma unroll
    for (int off = 1; off < 1024; off <<= 1) {
        int tmp = (t >= off) ? sm[t - off] : 0;
        __syncthreads();
        sm[t] += tmp;
        __syncthreads();
    }
    if (idx < NN) g_rowptr[idx] = sm[t] - v;   // exclusive
    if (t == 1023) g_blksum[blockIdx.x] = sm[t];
}

__global__ void scan2_kernel() {
    if (threadIdx.x == 0) {
        int run = 0;
        for (int i = 0; i < SCAN_B; i++) { int tv = g_blksum[i]; g_blksum[i] = run; run += tv; }
        g_rowptr[NN] = run;             // == EE
    }
}

__global__ void scan3_kernel() {
    int idx = blockIdx.x * 1024 + threadIdx.x;
    if (idx >= NN) return;
    int v = g_rowptr[idx] + g_blksum[blockIdx.x];
    g_rowptr[idx] = v;
    g_cursor[idx] = v;
}

__global__ void fill_kernel(const int* __restrict__ ei) {
    int e = blockIdx.x * blockDim.x + threadIdx.x;
    if (e >= EE) return;
    int s = ei[e];
    int d = ei[EE + e];
    int p = atomicAdd(&g_cursor[d], 1);
    g_csrc[p] = s;
}

// ---------------- gather: agg = (1+eps)*h + sum_neighbors h ------------------
// Warp handles 4 nodes; group g = lane>>3 owns node quad*4+g; sub = lane&7
// owns channels [sub*4, sub*4+4). Lean body -> high occupancy, latency hiding.
__global__ void __launch_bounds__(256)
gather_kernel(const float* __restrict__ eps, int l) {
    const float eps1 = 1.0f + eps[l];
    const int t = threadIdx.x;
    const int lane = t & 31;
    const int w = t >> 5;
    const int g = lane >> 3;
    const int sub = lane & 7;
    const unsigned FULL = 0xffffffffu;
    const uint2* __restrict__ hrows = (const uint2*)g_hh;  // 8 uint2 per row

    int gw = blockIdx.x * 8 + w;
    const int nquads = NN / 4;
    const int nw = FUSED_BLOCKS * 8;

    for (int q = gw; q < nquads; q += nw) {
        int i = q * 4 + g;
        int rs = g_rowptr[i];
        int re = g_rowptr[i + 1];
        int maxdeg = __reduce_max_sync(FULL, re - rs);

        uint2 raw = hrows[i * 8 + sub];
        float2 s01 = __half22float2(*(const __half2*)&raw.x);
        float2 s23 = __half22float2(*(const __half2*)&raw.y);
        float4 acc;
        acc.x = eps1 * s01.x; acc.y = eps1 * s01.y;
        acc.z = eps1 * s23.x; acc.w = eps1 * s23.y;

        int chunks = (maxdeg + 7) >> 3;
        for (int c = 0; c < chunks; ++c) {
            int base = rs + c * 8;
            int e = base + sub;
            int s = (e < re) ? __ldg(&g_csrc[e]) : 0;
            int cnt = re - base;
            #pragma unroll
            for (int r = 0; r < 8; ++r) {
                int sj = __shfl_sync(FULL, s, g * 8 + r);
                if (r < cnt) {
                    uint2 nb = hrows[sj * 8 + sub];
                    float2 f01 = __half22float2(*(const __half2*)&nb.x);
                    float2 f23 = __half22float2(*(const __half2*)&nb.y);
                    acc.x += f01.x; acc.y += f01.y;
                    acc.z += f23.x; acc.w += f23.y;
                }
            }
        }
        *(float4*)(g_z + i * HH + sub * 4) = acc;
    }
}

// ---------------- MLP: z = relu(agg@W1+b1)@W2+b2, + BN partials --------------
// Dense, coalesced float4 traffic; same 4-node/warp layout.
__global__ void __launch_bounds__(256)
mlp_kernel(const float* __restrict__ W1, const float* __restrict__ b1,
           const float* __restrict__ W2, const float* __restrict__ b2,
           int l) {
    __shared__ float W1s[HH * HH], W2s[HH * HH];
    __shared__ float b1s[HH], b2s[HH];
    __shared__ float4 redS[8][32], redQ[8][32];

    int t = threadIdx.x;
    const float* W1l = W1 + l * HH * HH;
    const float* W2l = W2 + l * HH * HH;
    #pragma unroll
    for (int i = t; i < HH * HH; i += 256) { W1s[i] = W1l[i]; W2s[i] = W2l[i]; }
    if (t < HH) { b1s[t] = b1[l * HH + t]; b2s[t] = b2[l * HH + t]; }
    __syncthreads();

    const int lane = t & 31;
    const int w = t >> 5;
    const int g = lane >> 3;
    const int sub = lane & 7;
    const unsigned FULL = 0xffffffffu;

    int gw = blockIdx.x * 8 + w;
    const int nquads = NN / 4;
    const int nw = FUSED_BLOCKS * 8;

    float4 wsum = make_float4(0.f, 0.f, 0.f, 0.f);
    float4 wsq  = make_float4(0.f, 0.f, 0.f, 0.f);

    for (int q = gw; q < nquads; q += nw) {
        int i = q * 4 + g;
        float4 acc = *(const float4*)(g_z + i * HH + sub * 4);

        // ---- MLP layer 1: z1 = relu(acc @ W1 + b1), 4 nodes batched ----
        float4 z1;
        z1.x = b1s[sub * 4 + 0]; z1.y = b1s[sub * 4 + 1];
        z1.z = b1s[sub * 4 + 2]; z1.w = b1s[sub * 4 + 3];
        #pragma unroll
        for (int r = 0; r < 8; ++r) {
            float bx = __shfl_sync(FULL, acc.x, g * 8 + r);
            float by = __shfl_sync(FULL, acc.y, g * 8 + r);
            float bz = __shfl_sync(FULL, acc.z, g * 8 + r);
            float bw = __shfl_sync(FULL, acc.w, g * 8 + r);
            const float4 w0 = *(const float4*)&W1s[(4 * r + 0) * HH + sub * 4];
            const float4 w1 = *(const float4*)&W1s[(4 * r + 1) * HH + sub * 4];
            const float4 w2 = *(const float4*)&W1s[(4 * r + 2) * HH + sub * 4];
            const float4 w3 = *(const float4*)&W1s[(4 * r + 3) * HH + sub * 4];
            z1.x = fmaf(bx, w0.x, z1.x); z1.x = fmaf(by, w1.x, z1.x);
            z1.x = fmaf(bz, w2.x, z1.x); z1.x = fmaf(bw, w3.x, z1.x);
            z1.y = fmaf(bx, w0.y, z1.y); z1.y = fmaf(by, w1.y, z1.y);
            z1.y = fmaf(bz, w2.y, z1.y); z1.y = fmaf(bw, w3.y, z1.y);
            z1.z = fmaf(bx, w0.z, z1.z); z1.z = fmaf(by, w1.z, z1.z);
            z1.z = fmaf(bz, w2.z, z1.z); z1.z = fmaf(bw, w3.z, z1.z);
            z1.w = fmaf(bx, w0.w, z1.w); z1.w = fmaf(by, w1.w, z1.w);
            z1.w = fmaf(bz, w2.w, z1.w); z1.w = fmaf(bw, w3.w, z1.w);
        }
        z1.x = fmaxf(z1.x, 0.f); z1.y = fmaxf(z1.y, 0.f);
        z1.z = fmaxf(z1.z, 0.f); z1.w = fmaxf(z1.w, 0.f);

        // ---- MLP layer 2: z2 = z1 @ W2 + b2 ----
        float4 z2;
        z2.x = b2s[sub * 4 + 0]; z2.y = b2s[sub * 4 + 1];
        z2.z = b2s[sub * 4 + 2]; z2.w = b2s[sub * 4 + 3];
        #pragma unroll
        for (int r = 0; r < 8; ++r) {
            float bx = __shfl_sync(FULL, z1.x, g * 8 + r);
            float by = __shfl_sync(FULL, z1.y, g * 8 + r);
            float bz = __shfl_sync(FULL, z1.z, g * 8 + r);
            float bw = __shfl_sync(FULL, z1.w, g * 8 + r);
            const float4 w0 = *(const float4*)&W2s[(4 * r + 0) * HH + sub * 4];
            const float4 w1 = *(const float4*)&W2s[(4 * r + 1) * HH + sub * 4];
            const float4 w2 = *(const float4*)&W2s[(4 * r + 2) * HH + sub * 4];
            const float4 w3 = *(const float4*)&W2s[(4 * r + 3) * HH + sub * 4];
            z2.x = fmaf(bx, w0.x, z2.x); z2.x = fmaf(by, w1.x, z2.x);
            z2.x = fmaf(bz, w2.x, z2.x); z2.x = fmaf(bw, w3.x, z2.x);
            z2.y = fmaf(bx, w0.y, z2.y); z2.y = fmaf(by, w1.y, z2.y);
            z2.y = fmaf(bz, w2.y, z2.y); z2.y = fmaf(bw, w3.y, z2.y);
            z2.z = fmaf(bx, w0.z, z2.z); z2.z = fmaf(by, w1.z, z2.z);
            z2.z = fmaf(bz, w2.z, z2.z); z2.z = fmaf(bw, w3.z, z2.z);
            z2.w = fmaf(bx, w0.w, z2.w); z2.w = fmaf(by, w1.w, z2.w);
            z2.w = fmaf(bz, w2.w, z2.w); z2.w = fmaf(bw, w3.w, z2.w);
        }

        *(float4*)(g_z + i * HH + sub * 4) = z2;
        wsum.x += z2.x; wsum.y += z2.y; wsum.z += z2.z; wsum.w += z2.w;
        wsq.x = fmaf(z2.x, z2.x, wsq.x); wsq.y = fmaf(z2.y, z2.y, wsq.y);
        wsq.z = fmaf(z2.z, z2.z, wsq.z); wsq.w = fmaf(z2.w, z2.w, wsq.w);
    }

    // block-level BN partial reduction
    redS[w][lane] = wsum;
    redQ[w][lane] = wsq;
    __syncthreads();
    if (w == 0) {
        float4 s = redS[0][lane], qv = redQ[0][lane];
        #pragma unroll
        for (int r = 1; r < 8; ++r) {
            float4 a = redS[r][lane], b = redQ[r][lane];
            s.x += a.x; s.y += a.y; s.z += a.z; s.w += a.w;
            qv.x += b.x; qv.y += b.y; qv.z += b.z; qv.w += b.w;
        }
        #pragma unroll
        for (int m = 8; m < 32; m <<= 1) {
            s.x += __shfl_xor_sync(FULL, s.x, m);
            s.y += __shfl_xor_sync(FULL, s.y, m);
            s.z += __shfl_xor_sync(FULL, s.z, m);
            s.w += __shfl_xor_sync(FULL, s.w, m);
            qv.x += __shfl_xor_sync(FULL, qv.x, m);
            qv.y += __shfl_xor_sync(FULL, qv.y, m);
            qv.z += __shfl_xor_sync(FULL, qv.z, m);
            qv.w += __shfl_xor_sync(FULL, qv.w, m);
        }
        if (g == 0) {
            *(float4*)&g_psum[blockIdx.x * HH + sub * 4] = s;
            *(float4*)&g_psq [blockIdx.x * HH + sub * 4] = qv;
        }
    }
}

// ---------------- BN finalize: fold into affine a*z + b ----------------------
__global__ void bn_finalize_kernel(const float* __restrict__ gamma,
                                   const float* __restrict__ beta, int l) {
    int k = threadIdx.x & 31;
    int r = threadIdx.x >> 5;       // 8 groups
    float s = 0.0f, q = 0.0f;
    for (int b = r; b < FUSED_BLOCKS; b += 8) {
        s += g_psum[b * HH + k];
        q += g_psq [b * HH + k];
    }
    __shared__ float ss[8][HH], qq[8][HH];
    ss[r][k] = s; qq[r][k] = q;
    __syncthreads();
    if (r == 0) {
        #pragma unroll
        for (int i = 1; i < 8; ++i) { s += ss[i][k]; q += qq[i][k]; }
        float mu  = s * (1.0f / (float)NN);
        float var = q * (1.0f / (float)NN) - mu * mu;
        float inv = rsqrtf(var + BN_EPS);
        float a = gamma[l * HH + k] * inv;
        g_bn_a[k] = a;
        g_bn_b[k] = fmaf(-mu, a, beta[l * HH + k]);
    }
}

// ---------------- BN apply + ReLU (+ pooling on last layer), fp16 h out ------
__global__ void bn_apply_kernel(const int* __restrict__ batch, int do_pool) {
    int idx = blockIdx.x * blockDim.x + threadIdx.x;   // float4 / uint2 index
    if (idx >= NN * 8) return;
    int sub = idx & 7;
    float4 z = *(const float4*)(g_z + idx * 4);
    float4 a = *(const float4*)&g_bn_a[sub * 4];
    float4 b = *(const float4*)&g_bn_b[sub * 4];
    float4 v;
    v.x = fmaxf(fmaf(a.x, z.x, b.x), 0.f);
    v.y = fmaxf(fmaf(a.y, z.y, b.y), 0.f);
    v.z = fmaxf(fmaf(a.z, z.z, b.z), 0.f);
    v.w = fmaxf(fmaf(a.w, z.w, b.w), 0.f);
    uint2 packed;
    *(__half2*)&packed.x = __floats2half2_rn(v.x, v.y);
    *(__half2*)&packed.y = __floats2half2_rn(v.z, v.w);
    ((uint2*)g_hh)[idx] = packed;
    if (do_pool) {
        int gidx = batch[idx >> 3];
        float* p = &g_pooled[gidx * HH + sub * 4];
        atomicAdd(p + 0, v.x);
        atomicAdd(p + 1, v.y);
        atomicAdd(p + 2, v.z);
        atomicAdd(p + 3, v.w);
    }
}

// ---------------- classifier -------------------------------------------------
__global__ void classifier_kernel(const float* __restrict__ W_cls,
                                  const float* __restrict__ b_cls,
                                  float* __restrict__ out) {
    int g = blockIdx.x * blockDim.x + threadIdx.x;
    if (g >= GG) return;
    float c0 = b_cls[0], c1 = b_cls[1];
    #pragma unroll
    for (int k = 0; k < HH; ++k) {
        float p = g_pooled[g * HH + k];
        c0 = fmaf(p, W_cls[k * CC + 0], c0);
        c1 = fmaf(p, W_cls[k * CC + 1], c1);
    }
    out[g * CC + 0] = c0;
    out[g * CC + 1] = c1;
}

// -----------------------------------------------------------------------------
extern "C" void kernel_launch(void* const* d_in, const int* in_sizes, int n_in,
                              void* d_out, int out_size) {
    const float* x     = (const float*)d_in[0];
    const int*   ei    = (const int*)  d_in[1];
    const int*   batch = (const int*)  d_in[2];
    const float* W_enc = (const float*)d_in[3];
    const float* b_enc = (const float*)d_in[4];
    const float* eps   = (const float*)d_in[5];
    const float* W1    = (const float*)d_in[6];
    const float* b1    = (const float*)d_in[7];
    const float* W2    = (const float*)d_in[8];
    const float* b2    = (const float*)d_in[9];
    const float* gamma = (const float*)d_in[10];
    const float* beta  = (const float*)d_in[11];
    const float* W_cls = (const float*)d_in[12];
    const float* b_cls = (const float*)d_in[13];
    float* out = (float*)d_out;

    init_enc_kernel<<<(NN * 16 + 255) / 256, 256>>>(x, W_enc, b_enc);

    hist_kernel<<<(EE + 255) / 256, 256>>>(ei);
    scan1_kernel<<<SCAN_B, 1024>>>();
    scan2_kernel<<<1, 32>>>();
    scan3_kernel<<<SCAN_B, 1024>>>();
    fill_kernel<<<(EE + 255) / 256, 256>>>(ei);

    for (int l = 0; l < LL; ++l) {
        gather_kernel<<<FUSED_BLOCKS, 256>>>(eps, l);
        mlp_kernel<<<FUSED_BLOCKS, 256>>>(W1, b1, W2, b2, l);
        bn_finalize_kernel<<<1, 256>>>(gamma, beta, l);
        bn_apply_kernel<<<(NN * 8 + 255) / 256, 256>>>(batch, l == LL - 1 ? 1 : 0);
    }

    classifier_kernel<<<(GG + 127) / 128, 128>>>(W_cls, b_cls, out);
}

// round 13
// speedup vs baseline: 1.1360x; 1.1360x over previous
#include <cuda_runtime.h>
#include <cuda_fp16.h>

#define NN 100000
#define EE 3200000
#define HH 32
#define LL 4
#define GG 1000
#define CC 2
#define BN_EPS 1e-5f

#define FUSED_BLOCKS 1184          // 8 * 148 SMs
#define SCAN_B 98                  // ceil(100000 / 1024)

// ---------------- scratch (static device globals; no allocation) -------------
__device__ __half g_hh[NN * HH];        // node features (post-activation), fp16
__device__ float  g_z[NN * HH];         // pre-BN MLP output, fp32
__device__ int    g_deg[NN];
__device__ int    g_rowptr[NN + 1];
__device__ int    g_cursor[NN];
__device__ int    g_csrc[EE];           // CSR-by-dst: source node per slot
__device__ int    g_blksum[SCAN_B];
__device__ float  g_pooled[GG * HH];
__device__ float  g_psum[FUSED_BLOCKS * HH];
__device__ float  g_psq [FUSED_BLOCKS * HH];
__device__ float  g_bn_a[HH];
__device__ float  g_bn_b[HH];
__device__ int    g_done[LL];           // last-block-done counters (self-resetting)

// ---------------- init (zero deg + pooled + done) + encoder, merged ----------
__global__ void init_enc_kernel(const float* __restrict__ x,
                                const float* __restrict__ W_enc,
                                const float* __restrict__ b_enc) {
    int idx = blockIdx.x * blockDim.x + threadIdx.x;
    if (idx < NN) g_deg[idx] = 0;
    if (idx < GG * HH) g_pooled[idx] = 0.0f;
    if (idx < LL) g_done[idx] = 0;
    if (idx == 0) g_rowptr[NN] = EE;               // total edges is constant
    if (idx < NN * 16) {                           // half2 index
        int i = idx >> 4;
        int k2 = idx & 15;
        float xv = x[i];
        float v0 = fmaf(xv, W_enc[2 * k2 + 0], b_enc[2 * k2 + 0]);
        float v1 = fmaf(xv, W_enc[2 * k2 + 1], b_enc[2 * k2 + 1]);
        *(__half2*)(g_hh + idx * 2) = __floats2half2_rn(v0, v1);
    }
}

// ---------------- CSR build --------------------------------------------------
__global__ void hist_kernel(const int* __restrict__ ei) {
    int e = blockIdx.x * blockDim.x + threadIdx.x;
    if (e >= EE) return;
    int d = ei[EE + e];                 // dst
    atomicAdd(&g_deg[d], 1);
}

__global__ void scan1_kernel() {
    __shared__ int sm[1024];
    int t = threadIdx.x;
    int idx = blockIdx.x * 1024 + t;
    int v = (idx < NN) ? g_deg[idx] : 0;
    sm[t] = v;
    __syncthreads();
    #pragma unroll
    for (int off = 1; off < 1024; off <<= 1) {
        int tmp = (t >= off) ? sm[t - off] : 0;
        __syncthreads();
        sm[t] += tmp;
        __syncthreads();
    }
    if (idx < NN) g_rowptr[idx] = sm[t] - v;   // exclusive (local)
    if (t == 1023) g_blksum[blockIdx.x] = sm[t];
}

// scan3: add cross-block prefix (computed in-kernel by warp 0) + init cursor
__global__ void scan3_kernel() {
    __shared__ int pfx;
    int t = threadIdx.x;
    if (t < 32) {
        int s = 0;
        for (int i = t; i < blockIdx.x; i += 32) s += g_blksum[i];
        #pragma unroll
        for (int m = 16; m; m >>= 1) s += __shfl_xor_sync(0xffffffffu, s, m);
        if (t == 0) pfx = s;
    }
    __syncthreads();
    int idx = blockIdx.x * 1024 + t;
    if (idx < NN) {
        int v = g_rowptr[idx] + pfx;
        g_rowptr[idx] = v;
        g_cursor[idx] = v;
    }
}

__global__ void fill_kernel(const int* __restrict__ ei) {
    int e = blockIdx.x * blockDim.x + threadIdx.x;
    if (e >= EE) return;
    int s = ei[e];
    int d = ei[EE + e];
    int p = atomicAdd(&g_cursor[d], 1);
    g_csrc[p] = s;
}

// ---------------- fused layer: gather + GIN + MLP + BN stats + finalize ------
// Warp processes 4 consecutive nodes. group g = lane>>3 owns node quad*4+g;
// sub = lane&7 owns channels [sub*4, sub*4+4). h rows are fp16 (64B).
// The LAST finishing block also folds BN stats into affine (a,b) — no extra
// single-block launch.
__global__ void __launch_bounds__(256)
fused_layer_kernel(const float* __restrict__ eps,
                   const float* __restrict__ W1, const float* __restrict__ b1,
                   const float* __restrict__ W2, const float* __restrict__ b2,
                   const float* __restrict__ gamma,
                   const float* __restrict__ beta,
                   int l) {
    __shared__ float W1s[HH * HH], W2s[HH * HH];
    __shared__ float b1s[HH], b2s[HH];
    __shared__ float4 redS[8][32], redQ[8][32];

    int t = threadIdx.x;
    const float* W1l = W1 + l * HH * HH;
    const float* W2l = W2 + l * HH * HH;
    #pragma unroll
    for (int i = t; i < HH * HH; i += 256) { W1s[i] = W1l[i]; W2s[i] = W2l[i]; }
    if (t < HH) { b1s[t] = b1[l * HH + t]; b2s[t] = b2[l * HH + t]; }
    __syncthreads();

    const float eps1 = 1.0f + eps[l];
    const int lane = t & 31;
    const int w = t >> 5;
    const int g = lane >> 3;
    const int sub = lane & 7;
    const unsigned FULL = 0xffffffffu;

    const uint2* __restrict__ hrows = (const uint2*)g_hh;  // 8 uint2 per row

    int gw = blockIdx.x * 8 + w;
    const int nquads = NN / 4;                 // 25000
    const int nw = FUSED_BLOCKS * 8;

    float4 wsum = make_float4(0.f, 0.f, 0.f, 0.f);
    float4 wsq  = make_float4(0.f, 0.f, 0.f, 0.f);

    for (int q = gw; q < nquads; q += nw) {
        int i = q * 4 + g;
        int rs = g_rowptr[i];
        int re = g_rowptr[i + 1];
        int maxdeg = __reduce_max_sync(FULL, re - rs);

        // self term
        uint2 raw = hrows[i * 8 + sub];
        float2 s01 = __half22float2(*(const __half2*)&raw.x);
        float2 s23 = __half22float2(*(const __half2*)&raw.y);
        float4 acc;
        acc.x = eps1 * s01.x; acc.y = eps1 * s01.y;
        acc.z = eps1 * s23.x; acc.w = eps1 * s23.y;

        // gather neighbors: 8 edges per group per chunk
        int chunks = (maxdeg + 7) >> 3;
        for (int c = 0; c < chunks; ++c) {
            int base = rs + c * 8;
            int e = base + sub;
            int s = (e < re) ? __ldg(&g_csrc[e]) : 0;
            int cnt = re - base;
            #pragma unroll
            for (int r = 0; r < 8; ++r) {
                int sj = __shfl_sync(FULL, s, g * 8 + r);
                if (r < cnt) {
                    uint2 nb = hrows[sj * 8 + sub];
                    float2 f01 = __half22float2(*(const __half2*)&nb.x);
                    float2 f23 = __half22float2(*(const __half2*)&nb.y);
                    acc.x += f01.x; acc.y += f01.y;
                    acc.z += f23.x; acc.w += f23.y;
                }
            }
        }

        // ---- MLP layer 1: z1 = relu(acc @ W1 + b1), 4 nodes batched ----
        float4 z1;
        z1.x = b1s[sub * 4 + 0]; z1.y = b1s[sub * 4 + 1];
        z1.z = b1s[sub * 4 + 2]; z1.w = b1s[sub * 4 + 3];
        #pragma unroll
        for (int r = 0; r < 8; ++r) {
            float bx = __shfl_sync(FULL, acc.x, g * 8 + r);
            float by = __shfl_sync(FULL, acc.y, g * 8 + r);
            float bz = __shfl_sync(FULL, acc.z, g * 8 + r);
            float bw = __shfl_sync(FULL, acc.w, g * 8 + r);
            const float4 w0 = *(const float4*)&W1s[(4 * r + 0) * HH + sub * 4];
            const float4 w1 = *(const float4*)&W1s[(4 * r + 1) * HH + sub * 4];
            const float4 w2 = *(const float4*)&W1s[(4 * r + 2) * HH + sub * 4];
            const float4 w3 = *(const float4*)&W1s[(4 * r + 3) * HH + sub * 4];
            z1.x = fmaf(bx, w0.x, z1.x); z1.x = fmaf(by, w1.x, z1.x);
            z1.x = fmaf(bz, w2.x, z1.x); z1.x = fmaf(bw, w3.x, z1.x);
            z1.y = fmaf(bx, w0.y, z1.y); z1.y = fmaf(by, w1.y, z1.y);
            z1.y = fmaf(bz, w2.y, z1.y); z1.y = fmaf(bw, w3.y, z1.y);
            z1.z = fmaf(bx, w0.z, z1.z); z1.z = fmaf(by, w1.z, z1.z);
            z1.z = fmaf(bz, w2.z, z1.z); z1.z = fmaf(bw, w3.z, z1.z);
            z1.w = fmaf(bx, w0.w, z1.w); z1.w = fmaf(by, w1.w, z1.w);
            z1.w = fmaf(bz, w2.w, z1.w); z1.w = fmaf(bw, w3.w, z1.w);
        }
        z1.x = fmaxf(z1.x, 0.f); z1.y = fmaxf(z1.y, 0.f);
        z1.z = fmaxf(z1.z, 0.f); z1.w = fmaxf(z1.w, 0.f);

        // ---- MLP layer 2: z2 = z1 @ W2 + b2 ----
        float4 z2;
        z2.x = b2s[sub * 4 + 0]; z2.y = b2s[sub * 4 + 1];
        z2.z = b2s[sub * 4 + 2]; z2.w = b2s[sub * 4 + 3];
        #pragma unroll
        for (int r = 0; r < 8; ++r) {
            float bx = __shfl_sync(FULL, z1.x, g * 8 + r);
            float by = __shfl_sync(FULL, z1.y, g * 8 + r);
            float bz = __shfl_sync(FULL, z1.z, g * 8 + r);
            float bw = __shfl_sync(FULL, z1.w, g * 8 + r);
            const float4 w0 = *(const float4*)&W2s[(4 * r + 0) * HH + sub * 4];
            const float4 w1 = *(const float4*)&W2s[(4 * r + 1) * HH + sub * 4];
            const float4 w2 = *(const float4*)&W2s[(4 * r + 2) * HH + sub * 4];
            const float4 w3 = *(const float4*)&W2s[(4 * r + 3) * HH + sub * 4];
            z2.x = fmaf(bx, w0.x, z2.x); z2.x = fmaf(by, w1.x, z2.x);
            z2.x = fmaf(bz, w2.x, z2.x); z2.x = fmaf(bw, w3.x, z2.x);
            z2.y = fmaf(bx, w0.y, z2.y); z2.y = fmaf(by, w1.y, z2.y);
            z2.y = fmaf(bz, w2.y, z2.y); z2.y = fmaf(bw, w3.y, z2.y);
            z2.z = fmaf(bx, w0.z, z2.z); z2.z = fmaf(by, w1.z, z2.z);
            z2.z = fmaf(bz, w2.z, z2.z); z2.z = fmaf(bw, w3.z, z2.z);
            z2.w = fmaf(bx, w0.w, z2.w); z2.w = fmaf(by, w1.w, z2.w);
            z2.w = fmaf(bz, w2.w, z2.w); z2.w = fmaf(bw, w3.w, z2.w);
        }

        *(float4*)(g_z + i * HH + sub * 4) = z2;
        wsum.x += z2.x; wsum.y += z2.y; wsum.z += z2.z; wsum.w += z2.w;
        wsq.x = fmaf(z2.x, z2.x, wsq.x); wsq.y = fmaf(z2.y, z2.y, wsq.y);
        wsq.z = fmaf(z2.z, z2.z, wsq.z); wsq.w = fmaf(z2.w, z2.w, wsq.w);
    }

    // ---- block-level BN partial reduction ----
    redS[w][lane] = wsum;
    redQ[w][lane] = wsq;
    __syncthreads();
    if (w == 0) {
        float4 s = redS[0][lane], qv = redQ[0][lane];
        #pragma unroll
        for (int r = 1; r < 8; ++r) {
            float4 a = redS[r][lane], b = redQ[r][lane];
            s.x += a.x; s.y += a.y; s.z += a.z; s.w += a.w;
            qv.x += b.x; qv.y += b.y; qv.z += b.z; qv.w += b.w;
        }
        #pragma unroll
        for (int m = 8; m < 32; m <<= 1) {
            s.x += __shfl_xor_sync(FULL, s.x, m);
            s.y += __shfl_xor_sync(FULL, s.y, m);
            s.z += __shfl_xor_sync(FULL, s.z, m);
            s.w += __shfl_xor_sync(FULL, s.w, m);
            qv.x += __shfl_xor_sync(FULL, qv.x, m);
            qv.y += __shfl_xor_sync(FULL, qv.y, m);
            qv.z += __shfl_xor_sync(FULL, qv.z, m);
            qv.w += __shfl_xor_sync(FULL, qv.w, m);
        }
        if (g == 0) {
            *(float4*)&g_psum[blockIdx.x * HH + sub * 4] = s;
            *(float4*)&g_psq [blockIdx.x * HH + sub * 4] = qv;
        }
    }

    // ---- last-block-done BN finalize (threadfence reduction pattern) ----
    __threadfence();
    __syncthreads();
    __shared__ int is_last;
    if (t == 0) is_last = (atomicAdd(&g_done[l], 1) == FUSED_BLOCKS - 1);
    __syncthreads();
    if (is_last) {
        int k = t & 31;
        int r = t >> 5;                 // 8 strides
        float s = 0.0f, q = 0.0f;
        for (int b = r; b < FUSED_BLOCKS; b += 8) {
            s += __ldcg(&g_psum[b * HH + k]);
            q += __ldcg(&g_psq [b * HH + k]);
        }
        __shared__ float ss[8][HH], qq[8][HH];
        ss[r][k] = s; qq[r][k] = q;
        __syncthreads();
        if (r == 0) {
            #pragma unroll
            for (int i = 1; i < 8; ++i) { s += ss[i][k]; q += qq[i][k]; }
            float mu  = s * (1.0f / (float)NN);
            float var = q * (1.0f / (float)NN) - mu * mu;
            float inv = rsqrtf(var + BN_EPS);
            float a = gamma[l * HH + k] * inv;
            g_bn_a[k] = a;
            g_bn_b[k] = fmaf(-mu, a, beta[l * HH + k]);
        }
        if (t == 0) g_done[l] = 0;      // reset for next graph replay
    }
}

// ---------------- BN apply + ReLU (+ pooling on last layer), fp16 h out ------
__global__ void bn_apply_kernel(const int* __restrict__ batch, int do_pool) {
    int idx = blockIdx.x * blockDim.x + threadIdx.x;   // float4 / uint2 index
    if (idx >= NN * 8) return;
    int sub = idx & 7;
    float4 z = *(const float4*)(g_z + idx * 4);
    float4 a = *(const float4*)&g_bn_a[sub * 4];
    float4 b = *(const float4*)&g_bn_b[sub * 4];
    float4 v;
    v.x = fmaxf(fmaf(a.x, z.x, b.x), 0.f);
    v.y = fmaxf(fmaf(a.y, z.y, b.y), 0.f);
    v.z = fmaxf(fmaf(a.z, z.z, b.z), 0.f);
    v.w = fmaxf(fmaf(a.w, z.w, b.w), 0.f);
    uint2 packed;
    *(__half2*)&packed.x = __floats2half2_rn(v.x, v.y);
    *(__half2*)&packed.y = __floats2half2_rn(v.z, v.w);
    ((uint2*)g_hh)[idx] = packed;

    if (do_pool) {
        const unsigned FULL = 0xffffffffu;
        int lane = threadIdx.x & 31;
        int g = lane >> 3;                      // node group within warp
        int gidx = batch[idx >> 3];
        // if all 4 nodes covered by this warp belong to one graph (common:
        // batch is sorted, ~100 nodes/graph), reduce across groups first.
        int g0 = __shfl_sync(FULL, gidx, lane & 7);      // group 0's graph id
        bool uni = __all_sync(FULL, gidx == g0);
        if (uni) {
            #pragma unroll
            for (int m = 8; m < 32; m <<= 1) {
                v.x += __shfl_xor_sync(FULL, v.x, m);
                v.y += __shfl_xor_sync(FULL, v.y, m);
                v.z += __shfl_xor_sync(FULL, v.z, m);
                v.w += __shfl_xor_sync(FULL, v.w, m);
            }
            if (g == 0) {
                float* p = &g_pooled[gidx * HH + sub * 4];
                atomicAdd(p + 0, v.x);
                atomicAdd(p + 1, v.y);
                atomicAdd(p + 2, v.z);
                atomicAdd(p + 3, v.w);
            }
        } else {
            float* p = &g_pooled[gidx * HH + sub * 4];
            atomicAdd(p + 0, v.x);
            atomicAdd(p + 1, v.y);
            atomicAdd(p + 2, v.z);
            atomicAdd(p + 3, v.w);
        }
    }
}

// ---------------- classifier -------------------------------------------------
__global__ void classifier_kernel(const float* __restrict__ W_cls,
                                  const float* __restrict__ b_cls,
                                  float* __restrict__ out) {
    int g = blockIdx.x * blockDim.x + threadIdx.x;
    if (g >= GG) return;
    float c0 = b_cls[0], c1 = b_cls[1];
    #pragma unroll
    for (int k = 0; k < HH; ++k) {
        float p = g_pooled[g * HH + k];
        c0 = fmaf(p, W_cls[k * CC + 0], c0);
        c1 = fmaf(p, W_cls[k * CC + 1], c1);
    }
    out[g * CC + 0] = c0;
    out[g * CC + 1] = c1;
}

// -----------------------------------------------------------------------------
extern "C" void kernel_launch(void* const* d_in, const int* in_sizes, int n_in,
                              void* d_out, int out_size) {
    const float* x     = (const float*)d_in[0];
    const int*   ei    = (const int*)  d_in[1];
    const int*   batch = (const int*)  d_in[2];
    const float* W_enc = (const float*)d_in[3];
    const float* b_enc = (const float*)d_in[4];
    const float* eps   = (const float*)d_in[5];
    const float* W1    = (const float*)d_in[6];
    const float* b1    = (const float*)d_in[7];
    const float* W2    = (const float*)d_in[8];
    const float* b2    = (const float*)d_in[9];
    const float* gamma = (const float*)d_in[10];
    const float* beta  = (const float*)d_in[11];
    const float* W_cls = (const float*)d_in[12];
    const float* b_cls = (const float*)d_in[13];
    float* out = (float*)d_out;

    init_enc_kernel<<<(NN * 16 + 255) / 256, 256>>>(x, W_enc, b_enc);

    hist_kernel<<<(EE + 255) / 256, 256>>>(ei);
    scan1_kernel<<<SCAN_B, 1024>>>();
    scan3_kernel<<<SCAN_B, 1024>>>();
    fill_kernel<<<(EE + 255) / 256, 256>>>(ei);

    for (int l = 0; l < LL; ++l) {
        fused_layer_kernel<<<FUSED_BLOCKS, 256>>>(eps, W1, b1, W2, b2,
                                                  gamma, beta, l);
        bn_apply_kernel<<<(NN * 8 + 255) / 256, 256>>>(batch, l == LL - 1 ? 1 : 0);
    }

    classifier_kernel<<<(GG + 127) / 128, 128>>>(W_cls, b_cls, out);
}

// round 15
// speedup vs baseline: 1.1423x; 1.0056x over previous
#include <cuda_runtime.h>
#include <cuda_fp16.h>

#define NN 100000
#define EE 3200000
#define HH 32
#define LL 4
#define GG 1000
#define CC 2
#define BN_EPS 1e-5f

#define FUSED_BLOCKS 1184          // 8 * 148 SMs
#define SCAN_B 98                  // ceil(100000 / 1024)

// ---------------- scratch (static device globals; no allocation) -------------
__device__ __half g_hh[NN * HH];        // node features (post-activation), fp16
__device__ float  g_z[NN * HH];         // pre-BN MLP output, fp32
__device__ int    g_deg[NN];
__device__ int    g_rowptr[NN + 1];
__device__ int    g_cursor[NN];
__device__ int    g_csrc[EE];           // CSR-by-dst: source node per slot
__device__ int    g_blksum[SCAN_B];
__device__ float  g_pooled[GG * HH];
__device__ float  g_psum[FUSED_BLOCKS * HH];
__device__ float  g_psq [FUSED_BLOCKS * HH];
__device__ float  g_bn_a[HH];
__device__ float  g_bn_b[HH];
__device__ int    g_done[LL];           // last-block-done counters (self-resetting)

// ---------------- init: zero deg + pooled + done ------------------------------
__global__ void init_kernel() {
    int idx = blockIdx.x * blockDim.x + threadIdx.x;
    if (idx < NN) g_deg[idx] = 0;
    if (idx < GG * HH) g_pooled[idx] = 0.0f;
    if (idx < LL) g_done[idx] = 0;
    if (idx == 0) g_rowptr[NN] = EE;               // total edges is constant
}

// ---------------- CSR build --------------------------------------------------
__global__ void hist_kernel(const int* __restrict__ ei) {
    int e = blockIdx.x * blockDim.x + threadIdx.x;
    if (e >= EE) return;
    int d = ei[EE + e];                 // dst
    atomicAdd(&g_deg[d], 1);
}

__global__ void scan1_kernel() {
    __shared__ int sm[1024];
    int t = threadIdx.x;
    int idx = blockIdx.x * 1024 + t;
    int v = (idx < NN) ? g_deg[idx] : 0;
    sm[t] = v;
    __syncthreads();
    #pragma unroll
    for (int off = 1; off < 1024; off <<= 1) {
        int tmp = (t >= off) ? sm[t - off] : 0;
        __syncthreads();
        sm[t] += tmp;
        __syncthreads();
    }
    if (idx < NN) g_rowptr[idx] = sm[t] - v;   // exclusive (local)
    if (t == 1023) g_blksum[blockIdx.x] = sm[t];
}

// scan3: add cross-block prefix (computed in-kernel by warp 0) + init cursor
__global__ void scan3_kernel() {
    __shared__ int pfx;
    int t = threadIdx.x;
    if (t < 32) {
        int s = 0;
        for (int i = t; i < blockIdx.x; i += 32) s += g_blksum[i];
        #pragma unroll
        for (int m = 16; m; m >>= 1) s += __shfl_xor_sync(0xffffffffu, s, m);
        if (t == 0) pfx = s;
    }
    __syncthreads();
    int idx = blockIdx.x * 1024 + t;
    if (idx < NN) {
        int v = g_rowptr[idx] + pfx;
        g_rowptr[idx] = v;
        g_cursor[idx] = v;
    }
}

__global__ void fill_kernel(const int* __restrict__ ei) {
    int e = blockIdx.x * blockDim.x + threadIdx.x;
    if (e >= EE) return;
    int s = ei[e];
    int d = ei[EE + e];
    int p = atomicAdd(&g_cursor[d], 1);
    g_csrc[p] = s;
}

// ============================================================================
// Shared MLP + BN-stat + last-block BN-finalize body (macro to reuse in both
// layer kernels). Expects: acc (float4, input), writes z2 to g_z, accumulates
// wsum/wsq. Layout: group g = lane>>3 owns node; sub = lane&7 owns 4 channels.
// ============================================================================
#define MLP_BODY(acc, i)                                                       \
    {                                                                          \
        float4 z1;                                                             \
        z1.x = b1s[sub * 4 + 0]; z1.y = b1s[sub * 4 + 1];                      \
        z1.z = b1s[sub * 4 + 2]; z1.w = b1s[sub * 4 + 3];                      \
        _Pragma("unroll")                                                      \
        for (int r = 0; r < 8; ++r) {                                          \
            float bx = __shfl_sync(FULL, acc.x, g * 8 + r);                    \
            float by = __shfl_sync(FULL, acc.y, g * 8 + r);                    \
            float bz = __shfl_sync(FULL, acc.z, g * 8 + r);                    \
            float bw = __shfl_sync(FULL, acc.w, g * 8 + r);                    \
            const float4 w0 = *(const float4*)&W1s[(4 * r + 0) * HH + sub * 4];\
            const float4 w1 = *(const float4*)&W1s[(4 * r + 1) * HH + sub * 4];\
            const float4 w2 = *(const float4*)&W1s[(4 * r + 2) * HH + sub * 4];\
            const float4 w3 = *(const float4*)&W1s[(4 * r + 3) * HH + sub * 4];\
            z1.x = fmaf(bx, w0.x, z1.x); z1.x = fmaf(by, w1.x, z1.x);          \
            z1.x = fmaf(bz, w2.x, z1.x); z1.x = fmaf(bw, w3.x, z1.x);          \
            z1.y = fmaf(bx, w0.y, z1.y); z1.y = fmaf(by, w1.y, z1.y);          \
            z1.y = fmaf(bz, w2.y, z1.y); z1.y = fmaf(bw, w3.y, z1.y);          \
            z1.z = fmaf(bx, w0.z, z1.z); z1.z = fmaf(by, w1.z, z1.z);          \
            z1.z = fmaf(bz, w2.z, z1.z); z1.z = fmaf(bw, w3.z, z1.z);          \
            z1.w = fmaf(bx, w0.w, z1.w); z1.w = fmaf(by, w1.w, z1.w);          \
            z1.w = fmaf(bz, w2.w, z1.w); z1.w = fmaf(bw, w3.w, z1.w);          \
        }                                                                      \
        z1.x = fmaxf(z1.x, 0.f); z1.y = fmaxf(z1.y, 0.f);                      \
        z1.z = fmaxf(z1.z, 0.f); z1.w = fmaxf(z1.w, 0.f);                      \
        float4 z2;                                                             \
        z2.x = b2s[sub * 4 + 0]; z2.y = b2s[sub * 4 + 1];                      \
        z2.z = b2s[sub * 4 + 2]; z2.w = b2s[sub * 4 + 3];                      \
        _Pragma("unroll")                                                      \
        for (int r = 0; r < 8; ++r) {                                          \
            float bx = __shfl_sync(FULL, z1.x, g * 8 + r);                     \
            float by = __shfl_sync(FULL, z1.y, g * 8 + r);                     \
            float bz = __shfl_sync(FULL, z1.z, g * 8 + r);                     \
            float bw = __shfl_sync(FULL, z1.w, g * 8 + r);                     \
            const float4 w0 = *(const float4*)&W2s[(4 * r + 0) * HH + sub * 4];\
            const float4 w1 = *(const float4*)&W2s[(4 * r + 1) * HH + sub * 4];\
            const float4 w2 = *(const float4*)&W2s[(4 * r + 2) * HH + sub * 4];\
            const float4 w3 = *(const float4*)&W2s[(4 * r + 3) * HH + sub * 4];\
            z2.x = fmaf(bx, w0.x, z2.x); z2.x = fmaf(by, w1.x, z2.x);          \
            z2.x = fmaf(bz, w2.x, z2.x); z2.x = fmaf(bw, w3.x, z2.x);          \
            z2.y = fmaf(bx, w0.y, z2.y); z2.y = fmaf(by, w1.y, z2.y);          \
            z2.y = fmaf(bz, w2.y, z2.y); z2.y = fmaf(bw, w3.y, z2.y);          \
            z2.z = fmaf(bx, w0.z, z2.z); z2.z = fmaf(by, w1.z, z2.z);          \
            z2.z = fmaf(bz, w2.z, z2.z); z2.z = fmaf(bw, w3.z, z2.z);          \
            z2.w = fmaf(bx, w0.w, z2.w); z2.w = fmaf(by, w1.w, z2.w);          \
            z2.w = fmaf(bz, w2.w, z2.w); z2.w = fmaf(bw, w3.w, z2.w);          \
        }                                                                      \
        *(float4*)(g_z + (i) * HH + sub * 4) = z2;                             \
        wsum.x += z2.x; wsum.y += z2.y; wsum.z += z2.z; wsum.w += z2.w;        \
        wsq.x = fmaf(z2.x, z2.x, wsq.x); wsq.y = fmaf(z2.y, z2.y, wsq.y);      \
        wsq.z = fmaf(z2.z, z2.z, wsq.z); wsq.w = fmaf(z2.w, z2.w, wsq.w);      \
    }

#define BN_TAIL(l)                                                             \
    {                                                                          \
        redS[w][lane] = wsum;                                                  \
        redQ[w][lane] = wsq;                                                   \
        __syncthreads();                                                       \
        if (w == 0) {                                                          \
            float4 s = redS[0][lane], qv = redQ[0][lane];                      \
            _Pragma("unroll")                                                  \
            for (int r = 1; r < 8; ++r) {                                      \
                float4 a = redS[r][lane], b = redQ[r][lane];                   \
                s.x += a.x; s.y += a.y; s.z += a.z; s.w += a.w;                \
                qv.x += b.x; qv.y += b.y; qv.z += b.z; qv.w += b.w;            \
            }                                                                  \
            _Pragma("unroll")                                                  \
            for (int m = 8; m < 32; m <<= 1) {                                 \
                s.x += __shfl_xor_sync(FULL, s.x, m);                          \
                s.y += __shfl_xor_sync(FULL, s.y, m);                          \
                s.z += __shfl_xor_sync(FULL, s.z, m);                          \
                s.w += __shfl_xor_sync(FULL, s.w, m);                          \
                qv.x += __shfl_xor_sync(FULL, qv.x, m);                        \
                qv.y += __shfl_xor_sync(FULL, qv.y, m);                        \
                qv.z += __shfl_xor_sync(FULL, qv.z, m);                        \
                qv.w += __shfl_xor_sync(FULL, qv.w, m);                        \
            }                                                                  \
            if (g == 0) {                                                      \
                *(float4*)&g_psum[blockIdx.x * HH + sub * 4] = s;              \
                *(float4*)&g_psq [blockIdx.x * HH + sub * 4] = qv;             \
            }                                                                  \
        }                                                                      \
        __threadfence();                                                       \
        __syncthreads();                                                       \
        __shared__ int is_last;                                                \
        if (t == 0) is_last = (atomicAdd(&g_done[l], 1) == FUSED_BLOCKS - 1);  \
        __syncthreads();                                                       \
        if (is_last) {                                                         \
            int k = t & 31;                                                    \
            int r = t >> 5;                                                    \
            float s = 0.0f, q = 0.0f;                                          \
            for (int b = r; b < FUSED_BLOCKS; b += 8) {                        \
                s += __ldcg(&g_psum[b * HH + k]);                              \
                q += __ldcg(&g_psq [b * HH + k]);                              \
            }                                                                  \
            __shared__ float ss[8][HH], qq[8][HH];                             \
            ss[r][k] = s; qq[r][k] = q;                                        \
            __syncthreads();                                                   \
            if (r == 0) {                                                      \
                _Pragma("unroll")                                              \
                for (int i2 = 1; i2 < 8; ++i2) { s += ss[i2][k]; q += qq[i2][k]; } \
                float mu  = s * (1.0f / (float)NN);                            \
                float var = q * (1.0f / (float)NN) - mu * mu;                  \
                float inv = rsqrtf(var + BN_EPS);                              \
                float a = gamma[(l) * HH + k] * inv;                           \
                g_bn_a[k] = a;                                                 \
                g_bn_b[k] = fmaf(-mu, a, beta[(l) * HH + k]);                  \
            }                                                                  \
            if (t == 0) g_done[l] = 0;                                         \
        }                                                                      \
    }

// ---------------- layer 0 (rank-1 encoder): scalar gather + MLP + BN ---------
// agg0 = (1+eps)*h0[i] + sum_j h0[j], h0 = x*w + b  (F_IN = 1)
//      = s1*w_k + s2*b_k   with s1 = (1+eps)x_i + sum x_j, s2 = (1+eps)+deg
__global__ void __launch_bounds__(256)
fused_layer0_kernel(const float* __restrict__ x,
                    const float* __restrict__ W_enc,
                    const float* __restrict__ b_enc,
                    const float* __restrict__ eps,
                    const float* __restrict__ W1, const float* __restrict__ b1,
                    const float* __restrict__ W2, const float* __restrict__ b2,
                    const float* __restrict__ gamma,
                    const float* __restrict__ beta) {
    __shared__ float W1s[HH * HH], W2s[HH * HH];
    __shared__ float b1s[HH], b2s[HH];
    __shared__ float wenc[HH], benc[HH];
    __shared__ float4 redS[8][32], redQ[8][32];

    int t = threadIdx.x;
    #pragma unroll
    for (int i = t; i < HH * HH; i += 256) { W1s[i] = W1[i]; W2s[i] = W2[i]; }
    if (t < HH) {
        b1s[t] = b1[t]; b2s[t] = b2[t];
        wenc[t] = W_enc[t]; benc[t] = b_enc[t];
    }
    __syncthreads();

    const float eps1 = 1.0f + eps[0];
    const int lane = t & 31;
    const int w = t >> 5;
    const int g = lane >> 3;
    const int sub = lane & 7;
    const unsigned FULL = 0xffffffffu;

    int gw = blockIdx.x * 8 + w;
    const int nquads = NN / 4;
    const int nw = FUSED_BLOCKS * 8;

    float4 wsum = make_float4(0.f, 0.f, 0.f, 0.f);
    float4 wsq  = make_float4(0.f, 0.f, 0.f, 0.f);

    for (int q = gw; q < nquads; q += nw) {
        int i = q * 4 + g;
        int rs = g_rowptr[i];
        int re = g_rowptr[i + 1];
        int deg = re - rs;

        // scalar gather: sum of x over neighbors (8 lanes cooperate)
        float psum = 0.0f;
        for (int base = rs + sub; base < re; base += 8) {
            int s = __ldg(&g_csrc[base]);
            psum += __ldg(&x[s]);
        }
        #pragma unroll
        for (int m = 1; m < 8; m <<= 1)
            psum += __shfl_xor_sync(FULL, psum, m);

        float s1 = fmaf(eps1, __ldg(&x[i]), psum);
        float s2 = eps1 + (float)deg;

        float4 wv = *(const float4*)&wenc[sub * 4];
        float4 bv = *(const float4*)&benc[sub * 4];
        float4 acc;
        acc.x = s1 * wv.x + s2 * bv.x;
        acc.y = s1 * wv.y + s2 * bv.y;
        acc.z = s1 * wv.z + s2 * bv.z;
        acc.w = s1 * wv.w + s2 * bv.w;

        MLP_BODY(acc, i)
    }

    BN_TAIL(0)
}

// ---------------- layers 1..3: fp16 row gather + MLP + BN --------------------
__global__ void __launch_bounds__(256)
fused_layer_kernel(const float* __restrict__ eps,
                   const float* __restrict__ W1, const float* __restrict__ b1,
                   const float* __restrict__ W2, const float* __restrict__ b2,
                   const float* __restrict__ gamma,
                   const float* __restrict__ beta,
                   int l) {
    __shared__ float W1s[HH * HH], W2s[HH * HH];
    __shared__ float b1s[HH], b2s[HH];
    __shared__ float4 redS[8][32], redQ[8][32];

    int t = threadIdx.x;
    const float* W1l = W1 + l * HH * HH;
    const float* W2l = W2 + l * HH * HH;
    #pragma unroll
    for (int i = t; i < HH * HH; i += 256) { W1s[i] = W1l[i]; W2s[i] = W2l[i]; }
    if (t < HH) { b1s[t] = b1[l * HH + t]; b2s[t] = b2[l * HH + t]; }
    __syncthreads();

    const float eps1 = 1.0f + eps[l];
    const int lane = t & 31;
    const int w = t >> 5;
    const int g = lane >> 3;
    const int sub = lane & 7;
    const unsigned FULL = 0xffffffffu;

    const uint2* __restrict__ hrows = (const uint2*)g_hh;  // 8 uint2 per row

    int gw = blockIdx.x * 8 + w;
    const int nquads = NN / 4;
    const int nw = FUSED_BLOCKS * 8;

    float4 wsum = make_float4(0.f, 0.f, 0.f, 0.f);
    float4 wsq  = make_float4(0.f, 0.f, 0.f, 0.f);

    for (int q = gw; q < nquads; q += nw) {
        int i = q * 4 + g;
        int rs = g_rowptr[i];
        int re = g_rowptr[i + 1];
        int maxdeg = __reduce_max_sync(FULL, re - rs);

        uint2 raw = hrows[i * 8 + sub];
        float2 s01 = __half22float2(*(const __half2*)&raw.x);
        float2 s23 = __half22float2(*(const __half2*)&raw.y);
        float4 acc;
        acc.x = eps1 * s01.x; acc.y = eps1 * s01.y;
        acc.z = eps1 * s23.x; acc.w = eps1 * s23.y;

        int chunks = (maxdeg + 7) >> 3;
        for (int c = 0; c < chunks; ++c) {
            int base = rs + c * 8;
            int e = base + sub;
            int s = (e < re) ? __ldg(&g_csrc[e]) : 0;
            int cnt = re - base;
            #pragma unroll
            for (int r = 0; r < 8; ++r) {
                int sj = __shfl_sync(FULL, s, g * 8 + r);
                if (r < cnt) {
                    uint2 nb = hrows[sj * 8 + sub];
                    float2 f01 = __half22float2(*(const __half2*)&nb.x);
                    float2 f23 = __half22float2(*(const __half2*)&nb.y);
                    acc.x += f01.x; acc.y += f01.y;
                    acc.z += f23.x; acc.w += f23.y;
                }
            }
        }

        MLP_BODY(acc, i)
    }

    BN_TAIL(l)
}

// ---------------- BN apply + ReLU (+ pooling on last layer), fp16 h out ------
__global__ void bn_apply_kernel(const int* __restrict__ batch, int do_pool) {
    int idx = blockIdx.x * blockDim.x + threadIdx.x;   // float4 / uint2 index
    if (idx >= NN * 8) return;
    int sub = idx & 7;
    float4 z = *(const float4*)(g_z + idx * 4);
    float4 a = *(const float4*)&g_bn_a[sub * 4];
    float4 b = *(const float4*)&g_bn_b[sub * 4];
    float4 v;
    v.x = fmaxf(fmaf(a.x, z.x, b.x), 0.f);
    v.y = fmaxf(fmaf(a.y, z.y, b.y), 0.f);
    v.z = fmaxf(fmaf(a.z, z.z, b.z), 0.f);
    v.w = fmaxf(fmaf(a.w, z.w, b.w), 0.f);
    uint2 packed;
    *(__half2*)&packed.x = __floats2half2_rn(v.x, v.y);
    *(__half2*)&packed.y = __floats2half2_rn(v.z, v.w);
    ((uint2*)g_hh)[idx] = packed;

    if (do_pool) {
        const unsigned FULL = 0xffffffffu;
        int lane = threadIdx.x & 31;
        int g = lane >> 3;
        int gidx = batch[idx >> 3];
        int g0 = __shfl_sync(FULL, gidx, lane & 7);
        bool uni = __all_sync(FULL, gidx == g0);
        if (uni) {
            #pragma unroll
            for (int m = 8; m < 32; m <<= 1) {
                v.x += __shfl_xor_sync(FULL, v.x, m);
                v.y += __shfl_xor_sync(FULL, v.y, m);
                v.z += __shfl_xor_sync(FULL, v.z, m);
                v.w += __shfl_xor_sync(FULL, v.w, m);
            }
            if (g == 0) {
                float* p = &g_pooled[gidx * HH + sub * 4];
                atomicAdd(p + 0, v.x);
                atomicAdd(p + 1, v.y);
                atomicAdd(p + 2, v.z);
                atomicAdd(p + 3, v.w);
            }
        } else {
            float* p = &g_pooled[gidx * HH + sub * 4];
            atomicAdd(p + 0, v.x);
            atomicAdd(p + 1, v.y);
            atomicAdd(p + 2, v.z);
            atomicAdd(p + 3, v.w);
        }
    }
}

// ---------------- classifier -------------------------------------------------
__global__ void classifier_kernel(const float* __restrict__ W_cls,
                                  const float* __restrict__ b_cls,
                                  float* __restrict__ out) {
    int g = blockIdx.x * blockDim.x + threadIdx.x;
    if (g >= GG) return;
    float c0 = b_cls[0], c1 = b_cls[1];
    #pragma unroll
    for (int k = 0; k < HH; ++k) {
        float p = g_pooled[g * HH + k];
        c0 = fmaf(p, W_cls[k * CC + 0], c0);
        c1 = fmaf(p, W_cls[k * CC + 1], c1);
    }
    out[g * CC + 0] = c0;
    out[g * CC + 1] = c1;
}

// -----------------------------------------------------------------------------
extern "C" void kernel_launch(void* const* d_in, const int* in_sizes, int n_in,
                              void* d_out, int out_size) {
    const float* x     = (const float*)d_in[0];
    const int*   ei    = (const int*)  d_in[1];
    const int*   batch = (const int*)  d_in[2];
    const float* W_enc = (const float*)d_in[3];
    const float* b_enc = (const float*)d_in[4];
    const float* eps   = (const float*)d_in[5];
    const float* W1    = (const float*)d_in[6];
    const float* b1    = (const float*)d_in[7];
    const float* W2    = (const float*)d_in[8];
    const float* b2    = (const float*)d_in[9];
    const float* gamma = (const float*)d_in[10];
    const float* beta  = (const float*)d_in[11];
    const float* W_cls = (const float*)d_in[12];
    const float* b_cls = (const float*)d_in[13];
    float* out = (float*)d_out;

    init_kernel<<<(NN + 255) / 256, 256>>>();

    hist_kernel<<<(EE + 255) / 256, 256>>>(ei);
    scan1_kernel<<<SCAN_B, 1024>>>();
    scan3_kernel<<<SCAN_B, 1024>>>();
    fill_kernel<<<(EE + 255) / 256, 256>>>(ei);

    // layer 0: rank-1 encoder folded into scalar gather
    fused_layer0_kernel<<<FUSED_BLOCKS, 256>>>(x, W_enc, b_enc, eps,
                                               W1, b1, W2, b2, gamma, beta);
    bn_apply_kernel<<<(NN * 8 + 255) / 256, 256>>>(batch, 0);

    for (int l = 1; l < LL; ++l) {
        fused_layer_kernel<<<FUSED_BLOCKS, 256>>>(eps, W1, b1, W2, b2,
                                                  gamma, beta, l);
        bn_apply_kernel<<<(NN * 8 + 255) / 256, 256>>>(batch, l == LL - 1 ? 1 : 0);
    }

    classifier_kernel<<<(GG + 127) / 128, 128>>>(W_cls, b_cls, out);
}

// round 16
// speedup vs baseline: 1.2300x; 1.0768x over previous
#include <cuda_runtime.h>
#include <cuda_fp16.h>

#define NN 100000
#define EE 3200000
#define HH 32
#define LL 4
#define GG 1000
#define CC 2
#define BN_EPS 1e-5f

#define FUSED_BLOCKS 1184          // 8 * 148 SMs
#define SCAN_B 98                  // ceil(100000 / 1024)
#define NOCT (NN / 8)              // 12500 octs of 8 nodes

// ---------------- scratch (static device globals; no allocation) -------------
__device__ __half g_hh[NN * HH];        // node features (post-activation), fp16
__device__ float  g_z[NN * HH];         // pre-BN MLP output, fp32
__device__ int    g_deg[NN];
__device__ int    g_rowptr[NN + 1];
__device__ int    g_cursor[NN];
__device__ int    g_csrc[EE];           // CSR-by-dst: source node per slot
__device__ int    g_blksum[SCAN_B];
__device__ float  g_psum[FUSED_BLOCKS * HH];
__device__ float  g_psq [FUSED_BLOCKS * HH];
__device__ float  g_bn_a[HH];
__device__ float  g_bn_b[HH];
__device__ int    g_done[LL];           // last-block-done counters (self-resetting)

// ---------------- init: zero deg + done, seed out with b_cls ------------------
__global__ void init_kernel(const float* __restrict__ b_cls,
                            float* __restrict__ out) {
    int idx = blockIdx.x * blockDim.x + threadIdx.x;
    if (idx < NN) g_deg[idx] = 0;
    if (idx < LL) g_done[idx] = 0;
    if (idx == 0) g_rowptr[NN] = EE;               // total edges is constant
    if (idx < GG) {
        out[idx * CC + 0] = b_cls[0];
        out[idx * CC + 1] = b_cls[1];
    }
}

// ---------------- CSR build --------------------------------------------------
__global__ void hist_kernel(const int* __restrict__ ei) {
    int e = blockIdx.x * blockDim.x + threadIdx.x;
    if (e >= EE) return;
    int d = ei[EE + e];                 // dst
    atomicAdd(&g_deg[d], 1);
}

__global__ void scan1_kernel() {
    __shared__ int sm[1024];
    int t = threadIdx.x;
    int idx = blockIdx.x * 1024 + t;
    int v = (idx < NN) ? g_deg[idx] : 0;
    sm[t] = v;
    __syncthreads();
    #pragma unroll
    for (int off = 1; off < 1024; off <<= 1) {
        int tmp = (t >= off) ? sm[t - off] : 0;
        __syncthreads();
        sm[t] += tmp;
        __syncthreads();
    }
    if (idx < NN) g_rowptr[idx] = sm[t] - v;   // exclusive (local)
    if (t == 1023) g_blksum[blockIdx.x] = sm[t];
}

// scan3: add cross-block prefix (computed in-kernel by warp 0) + init cursor
__global__ void scan3_kernel() {
    __shared__ int pfx;
    int t = threadIdx.x;
    if (t < 32) {
        int s = 0;
        for (int i = t; i < blockIdx.x; i += 32) s += g_blksum[i];
        #pragma unroll
        for (int m = 16; m; m >>= 1) s += __shfl_xor_sync(0xffffffffu, s, m);
        if (t == 0) pfx = s;
    }
    __syncthreads();
    int idx = blockIdx.x * 1024 + t;
    if (idx < NN) {
        int v = g_rowptr[idx] + pfx;
        g_rowptr[idx] = v;
        g_cursor[idx] = v;
    }
}

__global__ void fill_kernel(const int* __restrict__ ei) {
    int e = blockIdx.x * blockDim.x + threadIdx.x;
    if (e >= EE) return;
    int s = ei[e];
    int d = ei[EE + e];
    int p = atomicAdd(&g_cursor[d], 1);
    g_csrc[p] = s;
}

// ============================================================================
// 8-node MLP: two node-sets (A, B) share every weight load. Layout: group
// g = lane>>3 owns nodes iA = oct*8+g and iB = oct*8+4+g; sub = lane&7 owns
// channels [sub*4, sub*4+4).
// ============================================================================
#define MLP8_HALF(za, zb, srcA, srcB, Ws, bs)                                  \
    {                                                                          \
        za.x = bs[sub * 4 + 0]; za.y = bs[sub * 4 + 1];                        \
        za.z = bs[sub * 4 + 2]; za.w = bs[sub * 4 + 3];                        \
        zb.x = bs[sub * 4 + 0]; zb.y = bs[sub * 4 + 1];                        \
        zb.z = bs[sub * 4 + 2]; zb.w = bs[sub * 4 + 3];                        \
        _Pragma("unroll")                                                      \
        for (int r = 0; r < 8; ++r) {                                          \
            const float4 w0 = *(const float4*)&Ws[(4 * r + 0) * HH + sub * 4]; \
            const float4 w1 = *(const float4*)&Ws[(4 * r + 1) * HH + sub * 4]; \
            const float4 w2 = *(const float4*)&Ws[(4 * r + 2) * HH + sub * 4]; \
            const float4 w3 = *(const float4*)&Ws[(4 * r + 3) * HH + sub * 4]; \
            float bx = __shfl_sync(FULL, srcA.x, g * 8 + r);                   \
            float by = __shfl_sync(FULL, srcA.y, g * 8 + r);                   \
            float bz = __shfl_sync(FULL, srcA.z, g * 8 + r);                   \
            float bw = __shfl_sync(FULL, srcA.w, g * 8 + r);                   \
            za.x = fmaf(bx, w0.x, za.x); za.x = fmaf(by, w1.x, za.x);          \
            za.x = fmaf(bz, w2.x, za.x); za.x = fmaf(bw, w3.x, za.x);          \
            za.y = fmaf(bx, w0.y, za.y); za.y = fmaf(by, w1.y, za.y);          \
            za.y = fmaf(bz, w2.y, za.y); za.y = fmaf(bw, w3.y, za.y);          \
            za.z = fmaf(bx, w0.z, za.z); za.z = fmaf(by, w1.z, za.z);          \
            za.z = fmaf(bz, w2.z, za.z); za.z = fmaf(bw, w3.z, za.z);          \
            za.w = fmaf(bx, w0.w, za.w); za.w = fmaf(by, w1.w, za.w);          \
            za.w = fmaf(bz, w2.w, za.w); za.w = fmaf(bw, w3.w, za.w);          \
            bx = __shfl_sync(FULL, srcB.x, g * 8 + r);                         \
            by = __shfl_sync(FULL, srcB.y, g * 8 + r);                         \
            bz = __shfl_sync(FULL, srcB.z, g * 8 + r);                         \
            bw = __shfl_sync(FULL, srcB.w, g * 8 + r);                         \
            zb.x = fmaf(bx, w0.x, zb.x); zb.x = fmaf(by, w1.x, zb.x);          \
            zb.x = fmaf(bz, w2.x, zb.x); zb.x = fmaf(bw, w3.x, zb.x);          \
            zb.y = fmaf(bx, w0.y, zb.y); zb.y = fmaf(by, w1.y, zb.y);          \
            zb.y = fmaf(bz, w2.y, zb.y); zb.y = fmaf(bw, w3.y, zb.y);          \
            zb.z = fmaf(bx, w0.z, zb.z); zb.z = fmaf(by, w1.z, zb.z);          \
            zb.z = fmaf(bz, w2.z, zb.z); zb.z = fmaf(bw, w3.z, zb.z);          \
            zb.w = fmaf(bx, w0.w, zb.w); zb.w = fmaf(by, w1.w, zb.w);          \
            zb.w = fmaf(bz, w2.w, zb.w); zb.w = fmaf(bw, w3.w, zb.w);          \
        }                                                                      \
    }

#define MLP8_BODY(accA, accB, iA, iB)                                          \
    {                                                                          \
        float4 z1a, z1b;                                                       \
        MLP8_HALF(z1a, z1b, accA, accB, W1s, b1s)                              \
        z1a.x = fmaxf(z1a.x, 0.f); z1a.y = fmaxf(z1a.y, 0.f);                  \
        z1a.z = fmaxf(z1a.z, 0.f); z1a.w = fmaxf(z1a.w, 0.f);                  \
        z1b.x = fmaxf(z1b.x, 0.f); z1b.y = fmaxf(z1b.y, 0.f);                  \
        z1b.z = fmaxf(z1b.z, 0.f); z1b.w = fmaxf(z1b.w, 0.f);                  \
        float4 z2a, z2b;                                                       \
        MLP8_HALF(z2a, z2b, z1a, z1b, W2s, b2s)                                \
        *(float4*)(g_z + (iA) * HH + sub * 4) = z2a;                           \
        *(float4*)(g_z + (iB) * HH + sub * 4) = z2b;                           \
        wsum.x += z2a.x + z2b.x; wsum.y += z2a.y + z2b.y;                      \
        wsum.z += z2a.z + z2b.z; wsum.w += z2a.w + z2b.w;                      \
        wsq.x = fmaf(z2a.x, z2a.x, wsq.x); wsq.x = fmaf(z2b.x, z2b.x, wsq.x);  \
        wsq.y = fmaf(z2a.y, z2a.y, wsq.y); wsq.y = fmaf(z2b.y, z2b.y, wsq.y);  \
        wsq.z = fmaf(z2a.z, z2a.z, wsq.z); wsq.z = fmaf(z2b.z, z2b.z, wsq.z);  \
        wsq.w = fmaf(z2a.w, z2a.w, wsq.w); wsq.w = fmaf(z2b.w, z2b.w, wsq.w);  \
    }

#define BN_TAIL(l)                                                             \
    {                                                                          \
        redS[w][lane] = wsum;                                                  \
        redQ[w][lane] = wsq;                                                   \
        __syncthreads();                                                       \
        if (w == 0) {                                                          \
            float4 s = redS[0][lane], qv = redQ[0][lane];                      \
            _Pragma("unroll")                                                  \
            for (int r = 1; r < 8; ++r) {                                      \
                float4 a = redS[r][lane], b = redQ[r][lane];                   \
                s.x += a.x; s.y += a.y; s.z += a.z; s.w += a.w;                \
                qv.x += b.x; qv.y += b.y; qv.z += b.z; qv.w += b.w;            \
            }                                                                  \
            _Pragma("unroll")                                                  \
            for (int m = 8; m < 32; m <<= 1) {                                 \
                s.x += __shfl_xor_sync(FULL, s.x, m);                          \
                s.y += __shfl_xor_sync(FULL, s.y, m);                          \
                s.z += __shfl_xor_sync(FULL, s.z, m);                          \
                s.w += __shfl_xor_sync(FULL, s.w, m);                          \
                qv.x += __shfl_xor_sync(FULL, qv.x, m);                        \
                qv.y += __shfl_xor_sync(FULL, qv.y, m);                        \
                qv.z += __shfl_xor_sync(FULL, qv.z, m);                        \
                qv.w += __shfl_xor_sync(FULL, qv.w, m);                        \
            }                                                                  \
            if (g == 0) {                                                      \
                *(float4*)&g_psum[blockIdx.x * HH + sub * 4] = s;              \
                *(float4*)&g_psq [blockIdx.x * HH + sub * 4] = qv;             \
            }                                                                  \
        }                                                                      \
        __threadfence();                                                       \
        __syncthreads();                                                       \
        __shared__ int is_last;                                                \
        if (t == 0) is_last = (atomicAdd(&g_done[l], 1) == FUSED_BLOCKS - 1);  \
        __syncthreads();                                                       \
        if (is_last) {                                                         \
            int k = t & 31;                                                    \
            int r = t >> 5;                                                    \
            float s = 0.0f, q = 0.0f;                                          \
            for (int b = r; b < FUSED_BLOCKS; b += 8) {                        \
                s += __ldcg(&g_psum[b * HH + k]);                              \
                q += __ldcg(&g_psq [b * HH + k]);                              \
            }                                                                  \
            __shared__ float ss[8][HH], qq[8][HH];                             \
            ss[r][k] = s; qq[r][k] = q;                                        \
            __syncthreads();                                                   \
            if (r == 0) {                                                      \
                _Pragma("unroll")                                              \
                for (int i2 = 1; i2 < 8; ++i2) { s += ss[i2][k]; q += qq[i2][k]; } \
                float mu  = s * (1.0f / (float)NN);                            \
                float var = q * (1.0f / (float)NN) - mu * mu;                  \
                float inv = rsqrtf(var + BN_EPS);                              \
                float a = gamma[(l) * HH + k] * inv;                           \
                g_bn_a[k] = a;                                                 \
                g_bn_b[k] = fmaf(-mu, a, beta[(l) * HH + k]);                  \
            }                                                                  \
            if (t == 0) g_done[l] = 0;                                        \
        }                                                                      \
    }

// fp16 row gather for one node set (4 nodes, one per group)
#define GATHER_H(acc, i)                                                       \
    {                                                                          \
        int rs = g_rowptr[i];                                                  \
        int re = g_rowptr[(i) + 1];                                            \
        int maxdeg = __reduce_max_sync(FULL, re - rs);                         \
        uint2 raw = hrows[(i) * 8 + sub];                                      \
        float2 s01 = __half22float2(*(const __half2*)&raw.x);                  \
        float2 s23 = __half22float2(*(const __half2*)&raw.y);                  \
        acc.x = eps1 * s01.x; acc.y = eps1 * s01.y;                            \
        acc.z = eps1 * s23.x; acc.w = eps1 * s23.y;                            \
        int chunks = (maxdeg + 7) >> 3;                                        \
        for (int c = 0; c < chunks; ++c) {                                     \
            int base = rs + c * 8;                                             \
            int e = base + sub;                                                \
            int s = (e < re) ? __ldg(&g_csrc[e]) : 0;                          \
            int cnt = re - base;                                               \
            _Pragma("unroll")                                                  \
            for (int r = 0; r < 8; ++r) {                                      \
                int sj = __shfl_sync(FULL, s, g * 8 + r);                      \
                if (r < cnt) {                                                 \
                    uint2 nb = hrows[sj * 8 + sub];                            \
                    float2 f01 = __half22float2(*(const __half2*)&nb.x);       \
                    float2 f23 = __half22float2(*(const __half2*)&nb.y);       \
                    acc.x += f01.x; acc.y += f01.y;                            \
                    acc.z += f23.x; acc.w += f23.y;                            \
                }                                                              \
            }                                                                  \
        }                                                                      \
    }

// ---------------- layer 0 (rank-1 encoder): scalar gather + MLP + BN ---------
__global__ void __launch_bounds__(256)
fused_layer0_kernel(const float* __restrict__ x,
                    const float* __restrict__ W_enc,
                    const float* __restrict__ b_enc,
                    const float* __restrict__ eps,
                    const float* __restrict__ W1, const float* __restrict__ b1,
                    const float* __restrict__ W2, const float* __restrict__ b2,
                    const float* __restrict__ gamma,
                    const float* __restrict__ beta) {
    __shared__ float W1s[HH * HH], W2s[HH * HH];
    __shared__ float b1s[HH], b2s[HH];
    __shared__ float wenc[HH], benc[HH];
    __shared__ float4 redS[8][32], redQ[8][32];

    int t = threadIdx.x;
    #pragma unroll
    for (int i = t; i < HH * HH; i += 256) { W1s[i] = W1[i]; W2s[i] = W2[i]; }
    if (t < HH) {
        b1s[t] = b1[t]; b2s[t] = b2[t];
        wenc[t] = W_enc[t]; benc[t] = b_enc[t];
    }
    __syncthreads();

    const float eps1 = 1.0f + eps[0];
    const int lane = t & 31;
    const int w = t >> 5;
    const int g = lane >> 3;
    const int sub = lane & 7;
    const unsigned FULL = 0xffffffffu;

    int gw = blockIdx.x * 8 + w;
    const int nw = FUSED_BLOCKS * 8;

    float4 wsum = make_float4(0.f, 0.f, 0.f, 0.f);
    float4 wsq  = make_float4(0.f, 0.f, 0.f, 0.f);

    float4 wv = *(const float4*)&wenc[sub * 4];
    float4 bv = *(const float4*)&benc[sub * 4];

    for (int q = gw; q < NOCT; q += nw) {
        int iA = q * 8 + g;
        int iB = iA + 4;
        float4 accA, accB;

        #pragma unroll
        for (int half = 0; half < 2; ++half) {
            int i = half ? iB : iA;
            int rs = g_rowptr[i];
            int re = g_rowptr[i + 1];
            int deg = re - rs;
            float psum = 0.0f;
            for (int base = rs + sub; base < re; base += 8) {
                int s = __ldg(&g_csrc[base]);
                psum += __ldg(&x[s]);
            }
            #pragma unroll
            for (int m = 1; m < 8; m <<= 1)
                psum += __shfl_xor_sync(FULL, psum, m);
            float s1 = fmaf(eps1, __ldg(&x[i]), psum);
            float s2 = eps1 + (float)deg;
            float4 a;
            a.x = s1 * wv.x + s2 * bv.x;
            a.y = s1 * wv.y + s2 * bv.y;
            a.z = s1 * wv.z + s2 * bv.z;
            a.w = s1 * wv.w + s2 * bv.w;
            if (half) accB = a; else accA = a;
        }

        MLP8_BODY(accA, accB, iA, iB)
    }

    BN_TAIL(0)
}

// ---------------- layers 1..3: fp16 row gather + MLP + BN --------------------
__global__ void __launch_bounds__(256)
fused_layer_kernel(const float* __restrict__ eps,
                   const float* __restrict__ W1, const float* __restrict__ b1,
                   const float* __restrict__ W2, const float* __restrict__ b2,
                   const float* __restrict__ gamma,
                   const float* __restrict__ beta,
                   int l) {
    __shared__ float W1s[HH * HH], W2s[HH * HH];
    __shared__ float b1s[HH], b2s[HH];
    __shared__ float4 redS[8][32], redQ[8][32];

    int t = threadIdx.x;
    const float* W1l = W1 + l * HH * HH;
    const float* W2l = W2 + l * HH * HH;
    #pragma unroll
    for (int i = t; i < HH * HH; i += 256) { W1s[i] = W1l[i]; W2s[i] = W2l[i]; }
    if (t < HH) { b1s[t] = b1[l * HH + t]; b2s[t] = b2[l * HH + t]; }
    __syncthreads();

    const float eps1 = 1.0f + eps[l];
    const int lane = t & 31;
    const int w = t >> 5;
    const int g = lane >> 3;
    const int sub = lane & 7;
    const unsigned FULL = 0xffffffffu;

    const uint2* __restrict__ hrows = (const uint2*)g_hh;  // 8 uint2 per row

    int gw = blockIdx.x * 8 + w;
    const int nw = FUSED_BLOCKS * 8;

    float4 wsum = make_float4(0.f, 0.f, 0.f, 0.f);
    float4 wsq  = make_float4(0.f, 0.f, 0.f, 0.f);

    for (int q = gw; q < NOCT; q += nw) {
        int iA = q * 8 + g;
        int iB = iA + 4;
        float4 accA, accB;
        GATHER_H(accA, iA)
        GATHER_H(accB, iB)
        MLP8_BODY(accA, accB, iA, iB)
    }

    BN_TAIL(l)
}

// ---------------- BN apply + ReLU, fp16 h out; last layer also pools ---------
// Last layer: per-node y = h @ W_cls (2 scalars) reduced in-warp, atomically
// added straight into out (pre-seeded with b_cls).
__global__ void bn_apply_kernel(const int* __restrict__ batch,
                                const float* __restrict__ W_cls,
                                float* __restrict__ out,
                                int do_pool) {
    __shared__ float wc[HH * CC];
    if (threadIdx.x < HH * CC) wc[threadIdx.x] = W_cls[threadIdx.x];
    __syncthreads();

    int idx = blockIdx.x * blockDim.x + threadIdx.x;   // float4 / uint2 index
    if (idx >= NN * 8) return;
    int sub = idx & 7;
    float4 z = *(const float4*)(g_z + idx * 4);
    float4 a = *(const float4*)&g_bn_a[sub * 4];
    float4 b = *(const float4*)&g_bn_b[sub * 4];
    float4 v;
    v.x = fmaxf(fmaf(a.x, z.x, b.x), 0.f);
    v.y = fmaxf(fmaf(a.y, z.y, b.y), 0.f);
    v.z = fmaxf(fmaf(a.z, z.z, b.z), 0.f);
    v.w = fmaxf(fmaf(a.w, z.w, b.w), 0.f);
    uint2 packed;
    *(__half2*)&packed.x = __floats2half2_rn(v.x, v.y);
    *(__half2*)&packed.y = __floats2half2_rn(v.z, v.w);
    ((uint2*)g_hh)[idx] = packed;

    if (do_pool) {
        const unsigned FULL = 0xffffffffu;
        int lane = threadIdx.x & 31;
        int g = lane >> 3;
        int k0 = sub * 4;
        // per-lane partial of y = h_row @ W_cls (2 outputs)
        float y0 = v.x * wc[(k0 + 0) * CC + 0] + v.y * wc[(k0 + 1) * CC + 0]
                 + v.z * wc[(k0 + 2) * CC + 0] + v.w * wc[(k0 + 3) * CC + 0];
        float y1 = v.x * wc[(k0 + 0) * CC + 1] + v.y * wc[(k0 + 1) * CC + 1]
                 + v.z * wc[(k0 + 2) * CC + 1] + v.w * wc[(k0 + 3) * CC + 1];
        // reduce within the 8-lane group
        #pragma unroll
        for (int m = 1; m < 8; m <<= 1) {
            y0 += __shfl_xor_sync(FULL, y0, m);
            y1 += __shfl_xor_sync(FULL, y1, m);
        }
        int gidx = batch[idx >> 3];
        int g0 = __shfl_sync(FULL, gidx, lane & 7);
        bool uni = __all_sync(FULL, gidx == g0);
        if (uni) {
            #pragma unroll
            for (int m = 8; m < 32; m <<= 1) {
                y0 += __shfl_xor_sync(FULL, y0, m);
                y1 += __shfl_xor_sync(FULL, y1, m);
            }
            if (lane == 0) {
                atomicAdd(&out[gidx * CC + 0], y0);
                atomicAdd(&out[gidx * CC + 1], y1);
            }
        } else {
            if (sub == 0) {
                atomicAdd(&out[gidx * CC + 0], y0);
                atomicAdd(&out[gidx * CC + 1], y1);
            }
        }
    }
}

// -----------------------------------------------------------------------------
extern "C" void kernel_launch(void* const* d_in, const int* in_sizes, int n_in,
                              void* d_out, int out_size) {
    const float* x     = (const float*)d_in[0];
    const int*   ei    = (const int*)  d_in[1];
    const int*   batch = (const int*)  d_in[2];
    const float* W_enc = (const float*)d_in[3];
    const float* b_enc = (const float*)d_in[4];
    const float* eps   = (const float*)d_in[5];
    const float* W1    = (const float*)d_in[6];
    const float* b1    = (const float*)d_in[7];
    const float* W2    = (const float*)d_in[8];
    const float* b2    = (const float*)d_in[9];
    const float* gamma = (const float*)d_in[10];
    const float* beta  = (const float*)d_in[11];
    const float* W_cls = (const float*)d_in[12];
    const float* b_cls = (const float*)d_in[13];
    float* out = (float*)d_out;

    init_kernel<<<(NN + 255) / 256, 256>>>(b_cls, out);

    hist_kernel<<<(EE + 255) / 256, 256>>>(ei);
    scan1_kernel<<<SCAN_B, 1024>>>();
    scan3_kernel<<<SCAN_B, 1024>>>();
    fill_kernel<<<(EE + 255) / 256, 256>>>(ei);

    // layer 0: rank-1 encoder folded into scalar gather
    fused_layer0_kernel<<<FUSED_BLOCKS, 256>>>(x, W_enc, b_enc, eps,
                                               W1, b1, W2, b2, gamma, beta);
    bn_apply_kernel<<<(NN * 8 + 255) / 256, 256>>>(batch, W_cls, out, 0);

    for (int l = 1; l < LL; ++l) {
        fused_layer_kernel<<<FUSED_BLOCKS, 256>>>(eps, W1, b1, W2, b2,
                                                  gamma, beta, l);
        bn_apply_kernel<<<(NN * 8 + 255) / 256, 256>>>(batch, W_cls, out,
                                                       l == LL - 1 ? 1 : 0);
    }
}